// round 1
// baseline (speedup 1.0000x reference)
#include <cuda_runtime.h>
#include <math.h>

#define NQ   2048
#define NW   64
#define CCH  640
#define NITER 100

// ---------------- scratch (device globals; no allocation allowed) ----------------
__device__ float g_qnA[(NQ*5)*CCH];   // normalized query features, row (m*5+i), col c
__device__ float g_pnB[CCH*(NW*5)];   // normalized proto features, row c, col (w*5+j)
__device__ float g_qfA[(NQ*5)*CCH];   // raw query features, row (m*5+p), col c
__device__ float g_pfB[5*CCH*NW];     // raw proto features [p][c][w]
__device__ float g_sim[(size_t)NQ*NW*25];  // [m][w][i][j]
__device__ float g_comb[(size_t)NQ*NW*5];  // [m][w][p]

// ---------------- Kernel 1: patch-pool features + center + normalize ----------------
__global__ void __launch_bounds__(640) feat_kernel(const float* __restrict__ proto,
                                                   const float* __restrict__ query) {
    int b = blockIdx.x;          // 0..2047 query, 2048..2111 proto
    int c = threadIdx.x;         // channel 0..639
    const float* src = (b < NQ) ? (query + ((size_t)b*CCH + c)*25)
                                : (proto + ((size_t)(b-NQ)*CCH + c)*25);
    float v[25];
#pragma unroll
    for (int k = 0; k < 25; ++k) v[k] = src[k];

    float s02[5], s24[5], s14[5];
#pragma unroll
    for (int col = 0; col < 5; ++col) {
        s02[col] = v[col]      + v[5+col]  + v[10+col];
        s24[col] = v[10+col]   + v[15+col] + v[20+col];
        s14[col] = v[5+col] + v[10+col] + v[15+col] + v[20+col];
    }
    float fea[5];
    fea[0] = (s02[0]+s02[1]+s02[2]) * (1.f/9.f);                 // lt
    fea[1] = (s24[0]+s24[1]+s24[2]) * (1.f/9.f);                 // rt
    fea[2] = (s14[1]+s14[2]+s14[3]+s14[4]) * (1.f/16.f);         // mid (rows1-4, cols1-4)
    fea[3] = (s02[2]+s02[3]+s02[4]) * (1.f/9.f);                 // lb
    fea[4] = (s24[2]+s24[3]+s24[4]) * (1.f/9.f);                 // rb

    // raw features for the weight GEMM
    if (b < NQ) {
#pragma unroll
        for (int p = 0; p < 5; ++p) g_qfA[(size_t)(b*5+p)*CCH + c] = fea[p];
    } else {
        int w = b - NQ;
#pragma unroll
        for (int p = 0; p < 5; ++p) g_pfB[((size_t)p*CCH + c)*NW + w] = fea[p];
    }

    __shared__ float sred[5][20];
    __shared__ float sstat[5];
    int lane = c & 31, wid = c >> 5;

    // mean over channels (per p)
    float r[5];
#pragma unroll
    for (int p = 0; p < 5; ++p) r[p] = fea[p];
#pragma unroll
    for (int o = 16; o; o >>= 1)
#pragma unroll
        for (int p = 0; p < 5; ++p) r[p] += __shfl_down_sync(0xffffffffu, r[p], o);
    if (lane == 0)
#pragma unroll
        for (int p = 0; p < 5; ++p) sred[p][wid] = r[p];
    __syncthreads();
    if (c < 5) {
        float s = 0.f;
        for (int q = 0; q < 20; ++q) s += sred[c][q];
        sstat[c] = s * (1.f/640.f);
    }
    __syncthreads();
    float cent[5];
#pragma unroll
    for (int p = 0; p < 5; ++p) cent[p] = fea[p] - sstat[p];

    // norm over channels (per p)
#pragma unroll
    for (int p = 0; p < 5; ++p) r[p] = cent[p]*cent[p];
#pragma unroll
    for (int o = 16; o; o >>= 1)
#pragma unroll
        for (int p = 0; p < 5; ++p) r[p] += __shfl_down_sync(0xffffffffu, r[p], o);
    __syncthreads();   // all prior sred reads complete before rewrite
    if (lane == 0)
#pragma unroll
        for (int p = 0; p < 5; ++p) sred[p][wid] = r[p];
    __syncthreads();
    if (c < 5) {
        float s = 0.f;
        for (int q = 0; q < 20; ++q) s += sred[c][q];
        sstat[c] = 1.f / fmaxf(sqrtf(s), 1e-8f);
    }
    __syncthreads();

    if (b < NQ) {
#pragma unroll
        for (int i = 0; i < 5; ++i) g_qnA[(size_t)(b*5+i)*CCH + c] = cent[i]*sstat[i];
    } else {
        int w = b - NQ;
#pragma unroll
        for (int j = 0; j < 5; ++j) g_pnB[(size_t)c*(NW*5) + w*5 + j] = cent[j]*sstat[j];
    }
}

// ---------------- Kernel 2: tiled fp32 GEMM (MODE 0: sim, MODE 1: per-p comb) ----------------
#define BM 128
#define BN 64
#define BKK 16

template<int MODE>
__global__ void __launch_bounds__(256) gemm_kernel() {
    __shared__ float As[BKK][BM];
    __shared__ float Bs[BKK][BN];
    int tid = threadIdx.x;
    int bx = blockIdx.x, by = blockIdx.y, z = blockIdx.z;

    const float* A; const float* B; int lda, ldb;
    if (MODE == 0) { A = g_qnA;           lda = CCH;   B = g_pnB;                     ldb = NW*5; }
    else           { A = g_qfA + z*CCH;   lda = 5*CCH; B = g_pfB + (size_t)z*CCH*NW;  ldb = NW;   }

    int arow = tid >> 2;          // 0..63
    int acol = (tid & 3) * 4;     // 0,4,8,12
    int brow = tid >> 4;          // 0..15
    int bcol = (tid & 15) * 4;    // 0..60
    int ty = tid >> 4, tx = tid & 15;

    float acc[8][4];
#pragma unroll
    for (int i = 0; i < 8; ++i)
#pragma unroll
        for (int j = 0; j < 4; ++j) acc[i][j] = 0.f;

    const float* Ab = A + (size_t)(by*BM)*lda;
    const float* Bb = B + bx*BN;

    for (int k0 = 0; k0 < CCH; k0 += BKK) {
        float4 a0 = *(const float4*)(Ab + (size_t)arow*lda + k0 + acol);
        float4 a1 = *(const float4*)(Ab + (size_t)(arow+64)*lda + k0 + acol);
        float4 b0 = *(const float4*)(Bb + (size_t)(k0+brow)*ldb + bcol);
        __syncthreads();
        As[acol+0][arow]    = a0.x; As[acol+1][arow]    = a0.y;
        As[acol+2][arow]    = a0.z; As[acol+3][arow]    = a0.w;
        As[acol+0][arow+64] = a1.x; As[acol+1][arow+64] = a1.y;
        As[acol+2][arow+64] = a1.z; As[acol+3][arow+64] = a1.w;
        *(float4*)&Bs[brow][bcol] = b0;
        __syncthreads();
#pragma unroll
        for (int k = 0; k < BKK; ++k) {
            float a[8], bb[4];
            *(float4*)&a[0] = *(const float4*)&As[k][ty*8];
            *(float4*)&a[4] = *(const float4*)&As[k][ty*8+4];
            *(float4*)&bb[0] = *(const float4*)&Bs[k][tx*4];
#pragma unroll
            for (int i = 0; i < 8; ++i)
#pragma unroll
                for (int j = 0; j < 4; ++j) acc[i][j] = fmaf(a[i], bb[j], acc[i][j]);
        }
    }

    int row0 = by*BM + ty*8;
    int col0 = bx*BN + tx*4;
    if (MODE == 0) {
#pragma unroll
        for (int i = 0; i < 8; ++i) {
            int rr = row0 + i; int m = rr/5, ii = rr%5;
#pragma unroll
            for (int j = 0; j < 4; ++j) {
                int cc = col0 + j; int w = cc/5, jj = cc%5;
                g_sim[((size_t)(m*NW + w))*25 + ii*5 + jj] = acc[i][j];
            }
        }
    } else {
#pragma unroll
        for (int i = 0; i < 8; ++i)
#pragma unroll
            for (int j = 0; j < 4; ++j)
                g_comb[(size_t)(row0+i)*(NW*5) + (col0+j)*5 + z] = acc[i][j];
    }
}

// ---------------- Kernel 3: multiplicative Sinkhorn, one thread per (m,w) ----------------
// Log-domain reference: f = eps*(log a - lse((g - c)/eps)); g = eps*(log b - lse((f - c)/eps))
// Identical (u=e^{f/eps}, v=e^{g/eps}): u = a/(K v); v = b/(K^T u); K = exp(-c/eps) = exp(20*sim-20)
// a == b == normalize(relu(comb)+0.00101) * 5/sum  (weight_2^T == weight_1 algebraically)
__global__ void __launch_bounds__(256) sinkhorn_kernel(float* __restrict__ out) {
    int t = blockIdx.x*256 + threadIdx.x;   // m*64 + w, exactly 131072 threads

    float a[5]; float ws = 0.f;
#pragma unroll
    for (int p = 0; p < 5; ++p) {
        float cmb = g_comb[(size_t)t*5 + p];
        float wv = fmaxf(cmb, 0.f) + 0.00101f;
        a[p] = wv; ws += wv;
    }
    float sc = __fdividef(5.f, ws);
#pragma unroll
    for (int p = 0; p < 5; ++p) a[p] *= sc;

    float Km[25];
    const float* sp = g_sim + (size_t)t*25;
#pragma unroll
    for (int e = 0; e < 25; ++e) Km[e] = __expf(fmaf(20.f, sp[e], -20.f));

    float u[5], v[5];
#pragma unroll
    for (int j = 0; j < 5; ++j) v[j] = 1.f;

#pragma unroll 1
    for (int it = 0; it < NITER; ++it) {
#pragma unroll
        for (int i = 0; i < 5; ++i) {
            float s = 0.f;
#pragma unroll
            for (int j = 0; j < 5; ++j) s = fmaf(Km[i*5+j], v[j], s);
            u[i] = __fdividef(a[i], fmaxf(s, 1e-30f));
        }
#pragma unroll
        for (int j = 0; j < 5; ++j) {
            float s = 0.f;
#pragma unroll
            for (int i = 0; i < 5; ++i) s = fmaf(Km[i*5+j], u[i], s);
            v[j] = __fdividef(a[j], fmaxf(s, 1e-30f));
        }
    }

    // logits = sum(sim * flow) * T/P ; sim recovered from K: sim = 1 + 0.05*ln(K)
    float logit = 0.f;
#pragma unroll
    for (int i = 0; i < 5; ++i)
#pragma unroll
        for (int j = 0; j < 5; ++j) {
            float K = Km[i*5+j];
            float flow = u[i]*K*v[j];
            float s = fmaf(0.05f, __logf(K), 1.f);
            logit = fmaf(s, flow, logit);
        }
    out[t] = logit * 2.5f;
}

// ---------------- launch ----------------
extern "C" void kernel_launch(void* const* d_in, const int* in_sizes, int n_in,
                              void* d_out, int out_size) {
    const float* proto = (const float*)d_in[0];
    const float* query = (const float*)d_in[1];
    if (n_in >= 2 && in_sizes[0] > in_sizes[1]) {  // defensive: proto is the small one
        proto = (const float*)d_in[1];
        query = (const float*)d_in[0];
    }
    float* out = (float*)d_out;

    feat_kernel<<<NQ + NW, 640>>>(proto, query);
    gemm_kernel<0><<<dim3((NW*5)/BN, (NQ*5)/BM, 1), 256>>>();   // sim:  (5, 80)
    gemm_kernel<1><<<dim3(1, NQ/BM, 5), 256>>>();               // comb: (1, 16, 5)
    sinkhorn_kernel<<<(NQ*NW)/256, 256>>>(out);
}

// round 2
// speedup vs baseline: 1.0447x; 1.0447x over previous
#include <cuda_runtime.h>
#include <math.h>

#define NQ   2048
#define NW   64
#define CCH  640
#define NITER 100

typedef unsigned long long u64;

// ---------------- packed f32x2 helpers (Blackwell) ----------------
__device__ __forceinline__ u64 pack2(float lo, float hi) {
    u64 r; asm("mov.b64 %0, {%1,%2};" : "=l"(r) : "f"(lo), "f"(hi)); return r;
}
__device__ __forceinline__ void unpack2(u64 v, float& lo, float& hi) {
    asm("mov.b64 {%0,%1}, %2;" : "=f"(lo), "=f"(hi) : "l"(v));
}
__device__ __forceinline__ void ffma2(u64& d, u64 a, u64 b) {
    asm("fma.rn.f32x2 %0, %1, %2, %0;" : "+l"(d) : "l"(a), "l"(b));
}
__device__ __forceinline__ u64 ffma2r(u64 a, u64 b, u64 c) {
    u64 r; asm("fma.rn.f32x2 %0, %1, %2, %3;" : "=l"(r) : "l"(a), "l"(b), "l"(c)); return r;
}
__device__ __forceinline__ u64 fmul2(u64 a, u64 b) {
    u64 r; asm("mul.rn.f32x2 %0, %1, %2;" : "=l"(r) : "l"(a), "l"(b)); return r;
}

// ---------------- scratch (device globals; no allocation allowed) ----------------
__device__ float g_qnA[(NQ*5)*CCH];   // normalized query features, row (m*5+i), col c
__device__ float g_pnB[CCH*(NW*5)];   // normalized proto features, row c, col (w*5+j)
__device__ float g_qfA[(NQ*5)*CCH];   // raw query features, row (m*5+p), col c
__device__ float g_pfB[5*CCH*NW];     // raw proto features [p][c][w]
__device__ float g_sim[(size_t)NQ*NW*25];  // [m][w][i][j]
__device__ float g_comb[(size_t)NQ*NW*5];  // [m][w][p]

// ---------------- Kernel 1: patch-pool features (smem-staged, coalesced) ----------------
__global__ void __launch_bounds__(640) feat_kernel(const float* __restrict__ proto,
                                                   const float* __restrict__ query) {
    extern __shared__ float simg[];   // 16000 floats = one (640,5,5) image
    int b = blockIdx.x;               // 0..2047 query, 2048..2111 proto
    int c = threadIdx.x;              // channel 0..639

    const float4* src4 = (const float4*)((b < NQ) ? (query + (size_t)b*CCH*25)
                                                  : (proto + (size_t)(b-NQ)*CCH*25));
    float4* s4 = (float4*)simg;
#pragma unroll
    for (int i = c; i < (CCH*25)/4; i += 640) s4[i] = src4[i];
    __syncthreads();

    float v[25];
#pragma unroll
    for (int k = 0; k < 25; ++k) v[k] = simg[c*25 + k];   // 25c mod 32 bijective: conflict-free

    float s02[5], s24[5], s14[5];
#pragma unroll
    for (int col = 0; col < 5; ++col) {
        s02[col] = v[col]    + v[5+col]  + v[10+col];
        s24[col] = v[10+col] + v[15+col] + v[20+col];
        s14[col] = v[5+col] + v[10+col] + v[15+col] + v[20+col];
    }
    float fea[5];
    fea[0] = (s02[0]+s02[1]+s02[2]) * (1.f/9.f);                 // lt
    fea[1] = (s24[0]+s24[1]+s24[2]) * (1.f/9.f);                 // rt
    fea[2] = (s14[1]+s14[2]+s14[3]+s14[4]) * (1.f/16.f);         // mid
    fea[3] = (s02[2]+s02[3]+s02[4]) * (1.f/9.f);                 // lb
    fea[4] = (s24[2]+s24[3]+s24[4]) * (1.f/9.f);                 // rb

    if (b < NQ) {
#pragma unroll
        for (int p = 0; p < 5; ++p) g_qfA[(size_t)(b*5+p)*CCH + c] = fea[p];
    } else {
        int w = b - NQ;
#pragma unroll
        for (int p = 0; p < 5; ++p) g_pfB[((size_t)p*CCH + c)*NW + w] = fea[p];
    }

    __shared__ float sred[5][20];
    __shared__ float sstat[5];
    int lane = c & 31, wid = c >> 5;

    float r[5];
#pragma unroll
    for (int p = 0; p < 5; ++p) r[p] = fea[p];
#pragma unroll
    for (int o = 16; o; o >>= 1)
#pragma unroll
        for (int p = 0; p < 5; ++p) r[p] += __shfl_down_sync(0xffffffffu, r[p], o);
    if (lane == 0)
#pragma unroll
        for (int p = 0; p < 5; ++p) sred[p][wid] = r[p];
    __syncthreads();
    if (c < 5) {
        float s = 0.f;
        for (int q = 0; q < 20; ++q) s += sred[c][q];
        sstat[c] = s * (1.f/640.f);
    }
    __syncthreads();
    float cent[5];
#pragma unroll
    for (int p = 0; p < 5; ++p) cent[p] = fea[p] - sstat[p];

#pragma unroll
    for (int p = 0; p < 5; ++p) r[p] = cent[p]*cent[p];
#pragma unroll
    for (int o = 16; o; o >>= 1)
#pragma unroll
        for (int p = 0; p < 5; ++p) r[p] += __shfl_down_sync(0xffffffffu, r[p], o);
    __syncthreads();
    if (lane == 0)
#pragma unroll
        for (int p = 0; p < 5; ++p) sred[p][wid] = r[p];
    __syncthreads();
    if (c < 5) {
        float s = 0.f;
        for (int q = 0; q < 20; ++q) s += sred[c][q];
        sstat[c] = 1.f / fmaxf(sqrtf(s), 1e-8f);
    }
    __syncthreads();

    if (b < NQ) {
#pragma unroll
        for (int i = 0; i < 5; ++i) g_qnA[(size_t)(b*5+i)*CCH + c] = cent[i]*sstat[i];
    } else {
        int w = b - NQ;
#pragma unroll
        for (int j = 0; j < 5; ++j) g_pnB[(size_t)c*(NW*5) + w*5 + j] = cent[j]*sstat[j];
    }
}

// ---------------- Kernel 2: tiled GEMM with packed FFMA2 ----------------
#define BM 128
#define BN 64
#define BKK 16

template<int MODE>
__global__ void __launch_bounds__(256) gemm_kernel() {
    __shared__ float As[BKK][BM];
    __shared__ float Bs[BKK][BN];
    int tid = threadIdx.x;
    int bx = blockIdx.x, by = blockIdx.y, z = blockIdx.z;

    const float* A; const float* B; int lda, ldb;
    if (MODE == 0) { A = g_qnA;         lda = CCH;   B = g_pnB;                    ldb = NW*5; }
    else           { A = g_qfA + z*CCH; lda = 5*CCH; B = g_pfB + (size_t)z*CCH*NW; ldb = NW;   }

    int arow = tid >> 2;          // 0..63
    int acol = (tid & 3) * 4;     // 0,4,8,12
    int brow = tid >> 4;          // 0..15
    int bcol = (tid & 15) * 4;    // 0..60
    int ty = tid >> 4, tx = tid & 15;

    u64 acc[4][4];                // [i-pair][j], 8x4 thread tile as 4 row-pairs
#pragma unroll
    for (int i = 0; i < 4; ++i)
#pragma unroll
        for (int j = 0; j < 4; ++j) acc[i][j] = 0ull;

    const float* Ab = A + (size_t)(by*BM)*lda;
    const float* Bb = B + bx*BN;

    for (int k0 = 0; k0 < CCH; k0 += BKK) {
        float4 a0 = *(const float4*)(Ab + (size_t)arow*lda + k0 + acol);
        float4 a1 = *(const float4*)(Ab + (size_t)(arow+64)*lda + k0 + acol);
        float4 b0 = *(const float4*)(Bb + (size_t)(k0+brow)*ldb + bcol);
        __syncthreads();
        As[acol+0][arow]    = a0.x; As[acol+1][arow]    = a0.y;
        As[acol+2][arow]    = a0.z; As[acol+3][arow]    = a0.w;
        As[acol+0][arow+64] = a1.x; As[acol+1][arow+64] = a1.y;
        As[acol+2][arow+64] = a1.z; As[acol+3][arow+64] = a1.w;
        *(float4*)&Bs[brow][bcol] = b0;
        __syncthreads();
#pragma unroll
        for (int k = 0; k < BKK; ++k) {
            const u64* ap = (const u64*)&As[k][ty*8];   // 32B-aligned, row pairs
            u64 a2[4] = {ap[0], ap[1], ap[2], ap[3]};
            float4 bv = *(const float4*)&Bs[k][tx*4];
            u64 b2[4] = {pack2(bv.x,bv.x), pack2(bv.y,bv.y),
                         pack2(bv.z,bv.z), pack2(bv.w,bv.w)};
#pragma unroll
            for (int ip = 0; ip < 4; ++ip)
#pragma unroll
                for (int j = 0; j < 4; ++j) ffma2(acc[ip][j], a2[ip], b2[j]);
        }
    }

    int row0 = by*BM + ty*8;
    int col0 = bx*BN + tx*4;
#pragma unroll
    for (int ip = 0; ip < 4; ++ip) {
#pragma unroll
        for (int j = 0; j < 4; ++j) {
            float lo, hi; unpack2(acc[ip][j], lo, hi);
            int r_lo = row0 + 2*ip, r_hi = r_lo + 1;
            int cc = col0 + j;
            if (MODE == 0) {
                int m0 = r_lo/5, i0 = r_lo%5;
                int m1 = r_hi/5, i1 = r_hi%5;
                int w = cc/5, jj = cc%5;
                g_sim[((size_t)(m0*NW + w))*25 + i0*5 + jj] = lo;
                g_sim[((size_t)(m1*NW + w))*25 + i1*5 + jj] = hi;
            } else {
                g_comb[(size_t)r_lo*(NW*5) + cc*5 + z] = lo;
                g_comb[(size_t)r_hi*(NW*5) + cc*5 + z] = hi;
            }
        }
    }
}

// ---------------- Kernel 3: multiplicative Sinkhorn, 2 pairs/thread, f32x2 ----------------
// u = a/(K v); v = a/(K^T u); K = exp(20*sim - 20); a = normalize(relu(comb)+0.00101)*5/sum
__device__ __forceinline__ u64 rcp2_newton(u64 s) {
    float lo, hi; unpack2(s, lo, hi);
    lo = fmaxf(lo, 1e-33f); hi = fmaxf(hi, 1e-33f);
    float r0 = __int_as_float(0x7EF127EAu - __float_as_uint(lo));
    float r1 = __int_as_float(0x7EF127EAu - __float_as_uint(hi));
    u64 r  = pack2(r0, r1);
    u64 sg = pack2(lo, hi);
    u64 ns = sg ^ 0x8000000080000000ull;           // -s (packed sign flip)
    const u64 TWO2 = 0x4000000040000000ull;        // (2.0f, 2.0f)
    r = fmul2(r, ffma2r(ns, r, TWO2));             // Newton 1
    r = fmul2(r, ffma2r(ns, r, TWO2));             // Newton 2 (rel err ~6e-6)
    return r;
}

__global__ void __launch_bounds__(256) sinkhorn_kernel(float* __restrict__ out) {
    int t0 = (blockIdx.x*256 + threadIdx.x) * 2;   // pairs t0, t0+1

    // marginals a (per half)
    float alo[5], ahi[5];
    {
        float ws0 = 0.f, ws1 = 0.f;
#pragma unroll
        for (int p = 0; p < 5; ++p) {
            float c0 = g_comb[(size_t)t0*5 + p];
            float c1 = g_comb[(size_t)(t0+1)*5 + p];
            alo[p] = fmaxf(c0, 0.f) + 0.00101f; ws0 += alo[p];
            ahi[p] = fmaxf(c1, 0.f) + 0.00101f; ws1 += ahi[p];
        }
        float sc0 = __fdividef(5.f, ws0), sc1 = __fdividef(5.f, ws1);
#pragma unroll
        for (int p = 0; p < 5; ++p) { alo[p] *= sc0; ahi[p] *= sc1; }
    }
    u64 a2[5];
#pragma unroll
    for (int p = 0; p < 5; ++p) a2[p] = pack2(alo[p], ahi[p]);

    // Gibbs kernel, packed
    u64 K2[25];
    const float* sp0 = g_sim + (size_t)t0*25;
#pragma unroll
    for (int e = 0; e < 25; ++e) {
        float k0 = __expf(fmaf(20.f, sp0[e],    -20.f));
        float k1 = __expf(fmaf(20.f, sp0[25+e], -20.f));
        K2[e] = pack2(k0, k1);
    }

    u64 v2[5], u2[5];
    const u64 ONE2 = 0x3F8000003F800000ull;
#pragma unroll
    for (int j = 0; j < 5; ++j) v2[j] = ONE2;

#pragma unroll 1
    for (int it = 0; it < NITER; ++it) {
        // u = a / (K v)   — divides on MUFU pipe
#pragma unroll
        for (int i = 0; i < 5; ++i) {
            u64 s = 0ull;
#pragma unroll
            for (int j = 0; j < 5; ++j) ffma2(s, K2[i*5+j], v2[j]);
            float slo, shi; unpack2(s, slo, shi);
            slo = fmaxf(slo, 1e-33f); shi = fmaxf(shi, 1e-33f);
            u2[i] = pack2(__fdividef(alo[i], slo), __fdividef(ahi[i], shi));
        }
        // v = a / (K^T u) — divides via Newton on FMA pipe (pipe balance)
#pragma unroll
        for (int j = 0; j < 5; ++j) {
            u64 s = 0ull;
#pragma unroll
            for (int i = 0; i < 5; ++i) ffma2(s, K2[i*5+j], u2[i]);
            v2[j] = fmul2(a2[j], rcp2_newton(s));
        }
    }

    // logits = sum(sim * u_i K_ij v_j) * T/P ; sim = 1 + 0.05*ln(K)
    float ulo[5], uhi[5], vlo[5], vhi[5];
#pragma unroll
    for (int p = 0; p < 5; ++p) { unpack2(u2[p], ulo[p], uhi[p]); unpack2(v2[p], vlo[p], vhi[p]); }
    float L0 = 0.f, L1 = 0.f;
#pragma unroll
    for (int i = 0; i < 5; ++i)
#pragma unroll
        for (int j = 0; j < 5; ++j) {
            float k0, k1; unpack2(K2[i*5+j], k0, k1);
            float f0 = ulo[i]*k0*vlo[j];
            float f1 = uhi[i]*k1*vhi[j];
            L0 = fmaf(fmaf(0.05f, __logf(k0), 1.f), f0, L0);
            L1 = fmaf(fmaf(0.05f, __logf(k1), 1.f), f1, L1);
        }
    out[t0]   = L0 * 2.5f;
    out[t0+1] = L1 * 2.5f;
}

// ---------------- launch ----------------
extern "C" void kernel_launch(void* const* d_in, const int* in_sizes, int n_in,
                              void* d_out, int out_size) {
    const float* proto = (const float*)d_in[0];
    const float* query = (const float*)d_in[1];
    if (n_in >= 2 && in_sizes[0] > in_sizes[1]) {
        proto = (const float*)d_in[1];
        query = (const float*)d_in[0];
    }
    float* out = (float*)d_out;

    static bool attr_set = false;
    if (!attr_set) {
        cudaFuncSetAttribute(feat_kernel, cudaFuncAttributeMaxDynamicSharedMemorySize, 64000);
        attr_set = true;
    }

    feat_kernel<<<NQ + NW, 640, 64000>>>(proto, query);
    gemm_kernel<0><<<dim3((NW*5)/BN, (NQ*5)/BM, 1), 256>>>();   // sim:  (5, 80)
    gemm_kernel<1><<<dim3(1, NQ/BM, 5), 256>>>();               // comb: (1, 16, 5)
    sinkhorn_kernel<<<(NQ*NW)/512, 256>>>(out);                 // 2 pairs/thread
}

// round 4
// speedup vs baseline: 1.0984x; 1.0514x over previous
#include <cuda_runtime.h>
#include <math.h>
#include <stdint.h>

#define NQ   2048
#define NW   64
#define CCH  640
#define NITER 100

typedef unsigned long long u64;
typedef unsigned int u32;

// ---------------- packed f32x2 helpers (Blackwell) ----------------
__device__ __forceinline__ u64 pack2(float lo, float hi) {
    u64 r; asm("mov.b64 %0, {%1,%2};" : "=l"(r) : "f"(lo), "f"(hi)); return r;
}
__device__ __forceinline__ void unpack2(u64 v, float& lo, float& hi) {
    asm("mov.b64 {%0,%1}, %2;" : "=f"(lo), "=f"(hi) : "l"(v));
}
__device__ __forceinline__ void ffma2(u64& d, u64 a, u64 b) {
    asm("fma.rn.f32x2 %0, %1, %2, %0;" : "+l"(d) : "l"(a), "l"(b));
}
__device__ __forceinline__ u64 fadd2(u64 a, u64 b) {
    u64 r; asm("add.rn.f32x2 %0, %1, %2;" : "=l"(r) : "l"(a), "l"(b)); return r;
}
__device__ __forceinline__ u64 fmul2(u64 a, u64 b) {
    u64 r; asm("mul.rn.f32x2 %0, %1, %2;" : "=l"(r) : "l"(a), "l"(b)); return r;
}

// ---------------- scratch ----------------
__device__ float g_qnA[(NQ*5)*CCH];   // normalized query features, row (m*5+i), col c
__device__ float g_pnB[CCH*(NW*5)];   // normalized proto features, row c, col (w*5+j)
__device__ float g_qfA[(NQ*5)*CCH];   // raw query features, row (m*5+p), col c
__device__ float g_pfB[5*CCH*NW];     // raw proto features [p][c][w]
__device__ float g_sim[(size_t)NQ*NW*25];  // [m][w][i][j]
__device__ float g_comb[(size_t)NQ*NW*5];  // [m][w][p]

// ---------------- Kernel 1: patch-pool features ----------------
__global__ void __launch_bounds__(640) feat_kernel(const float* __restrict__ proto,
                                                   const float* __restrict__ query) {
    extern __shared__ float simg[];   // 16000 floats = one (640,5,5) image
    int b = blockIdx.x;               // 0..2047 query, 2048..2111 proto
    int c = threadIdx.x;              // channel 0..639

    const float4* src4 = (const float4*)((b < NQ) ? (query + (size_t)b*CCH*25)
                                                  : (proto + (size_t)(b-NQ)*CCH*25));
    float4* s4 = (float4*)simg;
#pragma unroll
    for (int i = c; i < (CCH*25)/4; i += 640) s4[i] = src4[i];
    __syncthreads();

    float v[25];
#pragma unroll
    for (int k = 0; k < 25; ++k) v[k] = simg[c*25 + k];

    float s02[5], s24[5], s14[5];
#pragma unroll
    for (int col = 0; col < 5; ++col) {
        s02[col] = v[col]    + v[5+col]  + v[10+col];
        s24[col] = v[10+col] + v[15+col] + v[20+col];
        s14[col] = v[5+col] + v[10+col] + v[15+col] + v[20+col];
    }
    float fea[5];
    fea[0] = (s02[0]+s02[1]+s02[2]) * (1.f/9.f);
    fea[1] = (s24[0]+s24[1]+s24[2]) * (1.f/9.f);
    fea[2] = (s14[1]+s14[2]+s14[3]+s14[4]) * (1.f/16.f);
    fea[3] = (s02[2]+s02[3]+s02[4]) * (1.f/9.f);
    fea[4] = (s24[2]+s24[3]+s24[4]) * (1.f/9.f);

    if (b < NQ) {
#pragma unroll
        for (int p = 0; p < 5; ++p) g_qfA[(size_t)(b*5+p)*CCH + c] = fea[p];
    } else {
        int w = b - NQ;
#pragma unroll
        for (int p = 0; p < 5; ++p) g_pfB[((size_t)p*CCH + c)*NW + w] = fea[p];
    }

    __shared__ float sred[5][20];
    __shared__ float sstat[5];
    int lane = c & 31, wid = c >> 5;

    float r[5];
#pragma unroll
    for (int p = 0; p < 5; ++p) r[p] = fea[p];
#pragma unroll
    for (int o = 16; o; o >>= 1)
#pragma unroll
        for (int p = 0; p < 5; ++p) r[p] += __shfl_down_sync(0xffffffffu, r[p], o);
    if (lane == 0)
#pragma unroll
        for (int p = 0; p < 5; ++p) sred[p][wid] = r[p];
    __syncthreads();
    if (c < 5) {
        float s = 0.f;
        for (int q = 0; q < 20; ++q) s += sred[c][q];
        sstat[c] = s * (1.f/640.f);
    }
    __syncthreads();
    float cent[5];
#pragma unroll
    for (int p = 0; p < 5; ++p) cent[p] = fea[p] - sstat[p];

#pragma unroll
    for (int p = 0; p < 5; ++p) r[p] = cent[p]*cent[p];
#pragma unroll
    for (int o = 16; o; o >>= 1)
#pragma unroll
        for (int p = 0; p < 5; ++p) r[p] += __shfl_down_sync(0xffffffffu, r[p], o);
    __syncthreads();
    if (lane == 0)
#pragma unroll
        for (int p = 0; p < 5; ++p) sred[p][wid] = r[p];
    __syncthreads();
    if (c < 5) {
        float s = 0.f;
        for (int q = 0; q < 20; ++q) s += sred[c][q];
        sstat[c] = 1.f / fmaxf(sqrtf(s), 1e-8f);
    }
    __syncthreads();

    if (b < NQ) {
#pragma unroll
        for (int i = 0; i < 5; ++i) g_qnA[(size_t)(b*5+i)*CCH + c] = cent[i]*sstat[i];
    } else {
        int w = b - NQ;
#pragma unroll
        for (int j = 0; j < 5; ++j) g_pnB[(size_t)c*(NW*5) + w*5 + j] = cent[j]*sstat[j];
    }
}

// ---------------- Kernel 2a: sim GEMM on tensor cores (tf32 x3) ----------------
// C(10240x320) = qnA(10240x640) * pnB(640x320), scattered into g_sim.
// tf32x3: x = hi + lo, acc += hi*hi + hi*lo + lo*hi  (error ~2^-22, fp32-equivalent)
#define TBM 128
#define TBN 64
#define TBK 32

__device__ __forceinline__ u32 to_tf32_bits(float x) {
    u32 r; asm("cvt.rna.tf32.f32 %0, %1;" : "=r"(r) : "f"(x)); return r;
}
__device__ __forceinline__ void mma_tf32(float4& d, u32 a0,u32 a1,u32 a2,u32 a3, u32 b0,u32 b1) {
    asm("mma.sync.aligned.m16n8k8.row.col.f32.tf32.tf32.f32 "
        "{%0,%1,%2,%3},{%4,%5,%6,%7},{%8,%9},{%0,%1,%2,%3};"
        : "+f"(d.x),"+f"(d.y),"+f"(d.z),"+f"(d.w)
        : "r"(a0),"r"(a1),"r"(a2),"r"(a3),"r"(b0),"r"(b1));
}

#define LDA_S 36   // As row stride (floats)
#define LDB_S 68   // Bs row stride (floats)

__global__ void __launch_bounds__(256) simgemm_kernel() {
    __shared__ float As[TBM][LDA_S];   // [m][k]
    __shared__ float Bs[TBK][LDB_S];   // [k][n]

    int tid = threadIdx.x;
    int bx = blockIdx.x;   // N tile: 0..4
    int by = blockIdx.y;   // M tile: 0..79
    int lane = tid & 31;
    int w = tid >> 5;          // 8 warps
    int warpM = w & 3;         // 0..3 -> 32 rows each
    int warpN = w >> 2;        // 0..1 -> 32 cols each
    int grp = lane >> 2;       // groupID 0..7
    int tig = lane & 3;        // thread-in-group 0..3

    float4 acc[2][4];
#pragma unroll
    for (int mt = 0; mt < 2; ++mt)
#pragma unroll
        for (int nt = 0; nt < 4; ++nt) acc[mt][nt] = make_float4(0.f,0.f,0.f,0.f);

    const float* Ab = g_qnA + (size_t)(by*TBM)*CCH;
    const float* Bb = g_pnB + bx*TBN;

    // gmem load indices
    int ar = tid >> 3;            // 0..31 (row within 32-row pass)
    int ac = (tid & 7) * 4;       // 0..28
    int br = tid >> 4;            // 0..15 (k row within pass)
    int bc = (tid & 15) * 4;      // 0..60

    for (int k0 = 0; k0 < CCH; k0 += TBK) {
        float4 a0 = *(const float4*)(Ab + (size_t)(ar     )*CCH + k0 + ac);
        float4 a1 = *(const float4*)(Ab + (size_t)(ar + 32)*CCH + k0 + ac);
        float4 a2v= *(const float4*)(Ab + (size_t)(ar + 64)*CCH + k0 + ac);
        float4 a3v= *(const float4*)(Ab + (size_t)(ar + 96)*CCH + k0 + ac);
        float4 b0 = *(const float4*)(Bb + (size_t)(k0 + br     )*(NW*5) + bc);
        float4 b1 = *(const float4*)(Bb + (size_t)(k0 + br + 16)*(NW*5) + bc);
        __syncthreads();
        *(float4*)&As[ar     ][ac] = a0;
        *(float4*)&As[ar + 32][ac] = a1;
        *(float4*)&As[ar + 64][ac] = a2v;
        *(float4*)&As[ar + 96][ac] = a3v;
        *(float4*)&Bs[br     ][bc] = b0;
        *(float4*)&Bs[br + 16][bc] = b1;
        __syncthreads();

#pragma unroll
        for (int kk = 0; kk < TBK; kk += 8) {
            // A fragments (hi/lo) for 2 m-tiles
            u32 ahi[2][4], alo[2][4];
#pragma unroll
            for (int mt = 0; mt < 2; ++mt) {
                int r0 = warpM*32 + mt*16;
                float e0 = As[r0 + grp    ][kk + tig    ];
                float e1 = As[r0 + grp + 8][kk + tig    ];
                float e2 = As[r0 + grp    ][kk + tig + 4];
                float e3 = As[r0 + grp + 8][kk + tig + 4];
                u32 h0 = to_tf32_bits(e0), h1 = to_tf32_bits(e1);
                u32 h2 = to_tf32_bits(e2), h3 = to_tf32_bits(e3);
                ahi[mt][0]=h0; alo[mt][0]=__float_as_uint(e0-__uint_as_float(h0));
                ahi[mt][1]=h1; alo[mt][1]=__float_as_uint(e1-__uint_as_float(h1));
                ahi[mt][2]=h2; alo[mt][2]=__float_as_uint(e2-__uint_as_float(h2));
                ahi[mt][3]=h3; alo[mt][3]=__float_as_uint(e3-__uint_as_float(h3));
            }
            // B fragments (hi/lo) for 4 n-tiles
            u32 bhi[4][2], blo[4][2];
#pragma unroll
            for (int nt = 0; nt < 4; ++nt) {
                int c0 = warpN*32 + nt*8 + grp;
                float e0 = Bs[kk + tig    ][c0];
                float e1 = Bs[kk + tig + 4][c0];
                u32 h0 = to_tf32_bits(e0), h1 = to_tf32_bits(e1);
                bhi[nt][0]=h0; blo[nt][0]=__float_as_uint(e0-__uint_as_float(h0));
                bhi[nt][1]=h1; blo[nt][1]=__float_as_uint(e1-__uint_as_float(h1));
            }
#pragma unroll
            for (int mt = 0; mt < 2; ++mt)
#pragma unroll
                for (int nt = 0; nt < 4; ++nt) {
                    mma_tf32(acc[mt][nt], ahi[mt][0],ahi[mt][1],ahi[mt][2],ahi[mt][3],
                             bhi[nt][0],bhi[nt][1]);
                    mma_tf32(acc[mt][nt], ahi[mt][0],ahi[mt][1],ahi[mt][2],ahi[mt][3],
                             blo[nt][0],blo[nt][1]);
                    mma_tf32(acc[mt][nt], alo[mt][0],alo[mt][1],alo[mt][2],alo[mt][3],
                             bhi[nt][0],bhi[nt][1]);
                }
        }
    }

    // epilogue: scatter C(row,col) -> g_sim[(m*64+w)*25 + i*5 + j]
#pragma unroll
    for (int mt = 0; mt < 2; ++mt) {
#pragma unroll
        for (int nt = 0; nt < 4; ++nt) {
            int row0 = by*TBM + warpM*32 + mt*16 + grp;
            int col0 = bx*TBN + warpN*32 + nt*8 + 2*tig;
            float vals[4] = {acc[mt][nt].x, acc[mt][nt].y, acc[mt][nt].z, acc[mt][nt].w};
#pragma unroll
            for (int e = 0; e < 4; ++e) {
                int row = row0 + (e >> 1)*8;
                int col = col0 + (e & 1);
                int m = row/5, ii = row%5, ww = col/5, jj = col%5;
                g_sim[((size_t)(m*NW + ww))*25 + ii*5 + jj] = vals[e];
            }
        }
    }
}

// ---------------- Kernel 2b: comb GEMM (FFMA2, per-p batched) ----------------
#define BM 128
#define BN 64
#define BKK 16

__global__ void __launch_bounds__(256) combgemm_kernel() {
    __shared__ float As[BKK][BM];
    __shared__ float Bs[BKK][BN];
    int tid = threadIdx.x;
    int by = blockIdx.y, z = blockIdx.z;

    const float* A = g_qfA + z*CCH;            int lda = 5*CCH;
    const float* B = g_pfB + (size_t)z*CCH*NW; int ldb = NW;

    int arow = tid >> 2;
    int acol = (tid & 3) * 4;
    int brow = tid >> 4;
    int bcol = (tid & 15) * 4;
    int ty = tid >> 4, tx = tid & 15;

    u64 acc[4][4];
#pragma unroll
    for (int i = 0; i < 4; ++i)
#pragma unroll
        for (int j = 0; j < 4; ++j) acc[i][j] = 0ull;

    const float* Ab = A + (size_t)(by*BM)*lda;
    const float* Bb = B;

    for (int k0 = 0; k0 < CCH; k0 += BKK) {
        float4 a0 = *(const float4*)(Ab + (size_t)arow*lda + k0 + acol);
        float4 a1 = *(const float4*)(Ab + (size_t)(arow+64)*lda + k0 + acol);
        float4 b0 = *(const float4*)(Bb + (size_t)(k0+brow)*ldb + bcol);
        __syncthreads();
        As[acol+0][arow]    = a0.x; As[acol+1][arow]    = a0.y;
        As[acol+2][arow]    = a0.z; As[acol+3][arow]    = a0.w;
        As[acol+0][arow+64] = a1.x; As[acol+1][arow+64] = a1.y;
        As[acol+2][arow+64] = a1.z; As[acol+3][arow+64] = a1.w;
        *(float4*)&Bs[brow][bcol] = b0;
        __syncthreads();
#pragma unroll
        for (int k = 0; k < BKK; ++k) {
            const u64* ap = (const u64*)&As[k][ty*8];
            u64 a2[4] = {ap[0], ap[1], ap[2], ap[3]};
            float4 bv = *(const float4*)&Bs[k][tx*4];
            u64 b2[4] = {pack2(bv.x,bv.x), pack2(bv.y,bv.y),
                         pack2(bv.z,bv.z), pack2(bv.w,bv.w)};
#pragma unroll
            for (int ip = 0; ip < 4; ++ip)
#pragma unroll
                for (int j = 0; j < 4; ++j) ffma2(acc[ip][j], a2[ip], b2[j]);
        }
    }

    int row0 = by*BM + ty*8;
    int col0 = tx*4;
#pragma unroll
    for (int ip = 0; ip < 4; ++ip)
#pragma unroll
        for (int j = 0; j < 4; ++j) {
            float lo, hi; unpack2(acc[ip][j], lo, hi);
            int r_lo = row0 + 2*ip, r_hi = r_lo + 1;
            int cc = col0 + j;
            g_comb[(size_t)r_lo*(NW*5) + cc*5 + z] = lo;
            g_comb[(size_t)r_hi*(NW*5) + cc*5 + z] = hi;
        }
}

// ---------------- Kernel 3: multiplicative Sinkhorn, 2 pairs/thread, f32x2 ----------------
__device__ __forceinline__ u64 div2(u64 a, u64 s) {
    float slo, shi; unpack2(s, slo, shi);
    slo = fmaxf(slo, 1e-37f); shi = fmaxf(shi, 1e-37f);
    float rlo, rhi;
    asm("rcp.approx.f32 %0, %1;" : "=f"(rlo) : "f"(slo));
    asm("rcp.approx.f32 %0, %1;" : "=f"(rhi) : "f"(shi));
    return fmul2(a, pack2(rlo, rhi));
}

__global__ void __launch_bounds__(128) sinkhorn_kernel(float* __restrict__ out) {
    int t0 = (blockIdx.x*128 + threadIdx.x) * 2;   // pairs t0, t0+1

    // marginals a = relu(comb)+0.00101, scaled to sum 5 (weight_2^T == weight_1)
    u64 a2[5];
    float alo[5], ahi[5];
    {
        float ws0 = 0.f, ws1 = 0.f;
#pragma unroll
        for (int p = 0; p < 5; ++p) {
            alo[p] = fmaxf(g_comb[(size_t)t0*5 + p],     0.f) + 0.00101f; ws0 += alo[p];
            ahi[p] = fmaxf(g_comb[(size_t)(t0+1)*5 + p], 0.f) + 0.00101f; ws1 += ahi[p];
        }
        float sc0 = __fdividef(5.f, ws0), sc1 = __fdividef(5.f, ws1);
#pragma unroll
        for (int p = 0; p < 5; ++p) a2[p] = pack2(alo[p]*sc0, ahi[p]*sc1);
    }

    // Gibbs kernel K = exp(20*sim - 20), packed over the two pairs
    u64 K2[25];
    const float* sp0 = g_sim + (size_t)t0*25;
#pragma unroll
    for (int e = 0; e < 25; ++e) {
        float k0 = __expf(fmaf(20.f, sp0[e],    -20.f));
        float k1 = __expf(fmaf(20.f, sp0[25+e], -20.f));
        K2[e] = pack2(k0, k1);
    }

    u64 v2[5], u2[5];
    const u64 ONE2 = 0x3F8000003F800000ull;
#pragma unroll
    for (int j = 0; j < 5; ++j) v2[j] = ONE2;

#pragma unroll 1
    for (int it = 0; it < NITER; ++it) {
        // u = a / (K v)  — two accumulation trees per dot (shorter dep chain)
#pragma unroll
        for (int i = 0; i < 5; ++i) {
            u64 s1 = fmul2(K2[i*5+0], v2[0]);
            u64 s2 = fmul2(K2[i*5+1], v2[1]);
            ffma2(s1, K2[i*5+2], v2[2]);
            ffma2(s2, K2[i*5+3], v2[3]);
            ffma2(s1, K2[i*5+4], v2[4]);
            u2[i] = div2(a2[i], fadd2(s1, s2));
        }
        // v = a / (K^T u)
#pragma unroll
        for (int j = 0; j < 5; ++j) {
            u64 s1 = fmul2(K2[0*5+j], u2[0]);
            u64 s2 = fmul2(K2[1*5+j], u2[1]);
            ffma2(s1, K2[2*5+j], u2[2]);
            ffma2(s2, K2[3*5+j], u2[3]);
            ffma2(s1, K2[4*5+j], u2[4]);
            v2[j] = div2(a2[j], fadd2(s1, s2));
        }
    }

    // logits = sum(sim * u_i K_ij v_j) * 2.5 ; reload sim (contiguous, cached)
    float ulo[5], uhi[5], vlo[5], vhi[5];
#pragma unroll
    for (int p = 0; p < 5; ++p) { unpack2(u2[p], ulo[p], uhi[p]); unpack2(v2[p], vlo[p], vhi[p]); }
    float L0 = 0.f, L1 = 0.f;
#pragma unroll
    for (int i = 0; i < 5; ++i)
#pragma unroll
        for (int j = 0; j < 5; ++j) {
            float k0, k1; unpack2(K2[i*5+j], k0, k1);
            L0 = fmaf(sp0[i*5+j]    * ulo[i], k0*vlo[j], L0);
            L1 = fmaf(sp0[25+i*5+j] * uhi[i], k1*vhi[j], L1);
        }
    out[t0]   = L0 * 2.5f;
    out[t0+1] = L1 * 2.5f;
}

// ---------------- launch ----------------
extern "C" void kernel_launch(void* const* d_in, const int* in_sizes, int n_in,
                              void* d_out, int out_size) {
    const float* proto = (const float*)d_in[0];
    const float* query = (const float*)d_in[1];
    if (n_in >= 2 && in_sizes[0] > in_sizes[1]) {
        proto = (const float*)d_in[1];
        query = (const float*)d_in[0];
    }
    float* out = (float*)d_out;

    static bool attr_set = false;
    if (!attr_set) {
        cudaFuncSetAttribute(feat_kernel, cudaFuncAttributeMaxDynamicSharedMemorySize, 64000);
        attr_set = true;
    }

    feat_kernel<<<NQ + NW, 640, 64000>>>(proto, query);
    simgemm_kernel<<<dim3((NW*5)/TBN, (NQ*5)/TBM, 1), 256>>>();   // (5, 80)
    combgemm_kernel<<<dim3(1, NQ/BM, 5), 256>>>();                // (1, 16, 5)
    sinkhorn_kernel<<<(NQ*NW)/256, 128>>>(out);                   // 2 pairs/thread
}

// round 5
// speedup vs baseline: 1.1374x; 1.0355x over previous
#include <cuda_runtime.h>
#include <math.h>
#include <stdint.h>

#define NQ   2048
#define NW   64
#define CCH  640
#define NITER 100

typedef unsigned long long u64;
typedef unsigned int u32;

// ---------------- small helpers ----------------
__device__ __forceinline__ u64 pack2(float lo, float hi) {
    u64 r; asm("mov.b64 %0, {%1,%2};" : "=l"(r) : "f"(lo), "f"(hi)); return r;
}
__device__ __forceinline__ void unpack2(u64 v, float& lo, float& hi) {
    asm("mov.b64 {%0,%1}, %2;" : "=f"(lo), "=f"(hi) : "l"(v));
}
__device__ __forceinline__ void ffma2(u64& d, u64 a, u64 b) {
    asm("fma.rn.f32x2 %0, %1, %2, %0;" : "+l"(d) : "l"(a), "l"(b));
}
__device__ __forceinline__ u32 to_tf32_bits(float x) {
    u32 r; asm("cvt.rna.tf32.f32 %0, %1;" : "=r"(r) : "f"(x)); return r;
}
__device__ __forceinline__ void mma_tf32(float4& d, u32 a0,u32 a1,u32 a2,u32 a3, u32 b0,u32 b1) {
    asm("mma.sync.aligned.m16n8k8.row.col.f32.tf32.tf32.f32 "
        "{%0,%1,%2,%3},{%4,%5,%6,%7},{%8,%9},{%0,%1,%2,%3};"
        : "+f"(d.x),"+f"(d.y),"+f"(d.z),"+f"(d.w)
        : "r"(a0),"r"(a1),"r"(a2),"r"(a3),"r"(b0),"r"(b1));
}

// ---------------- scratch ----------------
__device__ float g_qnA_hi[(NQ*5)*CCH];  // tf32-rounded normalized query feats
__device__ float g_qnA_lo[(NQ*5)*CCH];  // residual
__device__ float g_pnB_hi[CCH*(NW*5)];  // [c][w*5+j]
__device__ float g_pnB_lo[CCH*(NW*5)];
__device__ float g_qfA[(NQ*5)*CCH];     // raw query features, row (m*5+p), col c
__device__ float g_pfB[5*CCH*NW];       // raw proto features [p][c][w]
__device__ float g_sim[(size_t)NQ*NW*25];  // [m][w][i][j]
__device__ float g_comb[(size_t)NQ*NW*5];  // [m][w][p]

// ---------------- Kernel 1: patch-pool features ----------------
__global__ void __launch_bounds__(640) feat_kernel(const float* __restrict__ proto,
                                                   const float* __restrict__ query) {
    extern __shared__ float simg[];   // 16000 floats = one (640,5,5) image
    int b = blockIdx.x;               // 0..2047 query, 2048..2111 proto
    int c = threadIdx.x;              // channel 0..639

    const float4* src4 = (const float4*)((b < NQ) ? (query + (size_t)b*CCH*25)
                                                  : (proto + (size_t)(b-NQ)*CCH*25));
    float4* s4 = (float4*)simg;
#pragma unroll
    for (int i = c; i < (CCH*25)/4; i += 640) s4[i] = src4[i];
    __syncthreads();

    float v[25];
#pragma unroll
    for (int k = 0; k < 25; ++k) v[k] = simg[c*25 + k];   // 25c mod 32 bijective

    float s02[5], s24[5], s14[5];
#pragma unroll
    for (int col = 0; col < 5; ++col) {
        s02[col] = v[col]    + v[5+col]  + v[10+col];
        s24[col] = v[10+col] + v[15+col] + v[20+col];
        s14[col] = v[5+col] + v[10+col] + v[15+col] + v[20+col];
    }
    float fea[5];
    fea[0] = (s02[0]+s02[1]+s02[2]) * (1.f/9.f);
    fea[1] = (s24[0]+s24[1]+s24[2]) * (1.f/9.f);
    fea[2] = (s14[1]+s14[2]+s14[3]+s14[4]) * (1.f/16.f);
    fea[3] = (s02[2]+s02[3]+s02[4]) * (1.f/9.f);
    fea[4] = (s24[2]+s24[3]+s24[4]) * (1.f/9.f);

    if (b < NQ) {
#pragma unroll
        for (int p = 0; p < 5; ++p) g_qfA[(size_t)(b*5+p)*CCH + c] = fea[p];
    } else {
        int w = b - NQ;
#pragma unroll
        for (int p = 0; p < 5; ++p) g_pfB[((size_t)p*CCH + c)*NW + w] = fea[p];
    }

    __shared__ float sred[5][20];
    __shared__ float sstat[5];
    int lane = c & 31, wid = c >> 5;

    float r[5];
#pragma unroll
    for (int p = 0; p < 5; ++p) r[p] = fea[p];
#pragma unroll
    for (int o = 16; o; o >>= 1)
#pragma unroll
        for (int p = 0; p < 5; ++p) r[p] += __shfl_down_sync(0xffffffffu, r[p], o);
    if (lane == 0)
#pragma unroll
        for (int p = 0; p < 5; ++p) sred[p][wid] = r[p];
    __syncthreads();
    if (c < 5) {
        float s = 0.f;
        for (int q = 0; q < 20; ++q) s += sred[c][q];
        sstat[c] = s * (1.f/640.f);
    }
    __syncthreads();
    float cent[5];
#pragma unroll
    for (int p = 0; p < 5; ++p) cent[p] = fea[p] - sstat[p];

#pragma unroll
    for (int p = 0; p < 5; ++p) r[p] = cent[p]*cent[p];
#pragma unroll
    for (int o = 16; o; o >>= 1)
#pragma unroll
        for (int p = 0; p < 5; ++p) r[p] += __shfl_down_sync(0xffffffffu, r[p], o);
    __syncthreads();
    if (lane == 0)
#pragma unroll
        for (int p = 0; p < 5; ++p) sred[p][wid] = r[p];
    __syncthreads();
    if (c < 5) {
        float s = 0.f;
        for (int q = 0; q < 20; ++q) s += sred[c][q];
        sstat[c] = 1.f / fmaxf(sqrtf(s), 1e-8f);
    }
    __syncthreads();

    if (b < NQ) {
#pragma unroll
        for (int i = 0; i < 5; ++i) {
            float q = cent[i]*sstat[i];
            u32 h = to_tf32_bits(q);
            size_t idx = (size_t)(b*5+i)*CCH + c;
            g_qnA_hi[idx] = __uint_as_float(h);
            g_qnA_lo[idx] = q - __uint_as_float(h);
        }
    } else {
        int w = b - NQ;
#pragma unroll
        for (int j = 0; j < 5; ++j) {
            float q = cent[j]*sstat[j];
            u32 h = to_tf32_bits(q);
            size_t idx = (size_t)c*(NW*5) + w*5 + j;
            g_pnB_hi[idx] = __uint_as_float(h);
            g_pnB_lo[idx] = q - __uint_as_float(h);
        }
    }
}

// ---------------- Kernel 2: mega GEMM  (bx<5: sim tf32x3, bx==5: comb FFMA2) ----------------
#define TBM 128
#define TBN 64
#define TBK 32
#define LDA_S 36
#define LDB_S 68
#define SMEM_GEMM ((2*TBM*LDA_S + 2*TBK*LDB_S)*4)   // 54272 B

__global__ void __launch_bounds__(256) gemm_mega() {
    extern __shared__ float sm[];
    int tid = threadIdx.x;
    int bx = blockIdx.x, by = blockIdx.y;

    if (bx < 5) {
        // ---------- sim GEMM: C(10240x320) = qn(10240x640) * pn(640x320), tf32x3 ----------
        float* As_hi = sm;
        float* As_lo = sm + TBM*LDA_S;
        float* Bs_hi = sm + 2*TBM*LDA_S;
        float* Bs_lo = sm + 2*TBM*LDA_S + TBK*LDB_S;

        int lane = tid & 31;
        int w = tid >> 5;
        int warpM = w & 3;
        int warpN = w >> 2;
        int grp = lane >> 2;
        int tig = lane & 3;

        float4 acc[2][4];
#pragma unroll
        for (int mt = 0; mt < 2; ++mt)
#pragma unroll
            for (int nt = 0; nt < 4; ++nt) acc[mt][nt] = make_float4(0.f,0.f,0.f,0.f);

        const float* Ah = g_qnA_hi + (size_t)(by*TBM)*CCH;
        const float* Al = g_qnA_lo + (size_t)(by*TBM)*CCH;
        const float* Bh = g_pnB_hi + bx*TBN;
        const float* Bl = g_pnB_lo + bx*TBN;

        int ar = tid >> 3;            // 0..31
        int ac = (tid & 7) * 4;       // 0..28
        int br = tid >> 4;            // 0..15
        int bc = (tid & 15) * 4;      // 0..60

        for (int k0 = 0; k0 < CCH; k0 += TBK) {
            float4 h0 = *(const float4*)(Ah + (size_t)(ar     )*CCH + k0 + ac);
            float4 h1 = *(const float4*)(Ah + (size_t)(ar + 32)*CCH + k0 + ac);
            float4 h2 = *(const float4*)(Ah + (size_t)(ar + 64)*CCH + k0 + ac);
            float4 h3 = *(const float4*)(Ah + (size_t)(ar + 96)*CCH + k0 + ac);
            float4 l0 = *(const float4*)(Al + (size_t)(ar     )*CCH + k0 + ac);
            float4 l1 = *(const float4*)(Al + (size_t)(ar + 32)*CCH + k0 + ac);
            float4 l2 = *(const float4*)(Al + (size_t)(ar + 64)*CCH + k0 + ac);
            float4 l3 = *(const float4*)(Al + (size_t)(ar + 96)*CCH + k0 + ac);
            float4 bh0 = *(const float4*)(Bh + (size_t)(k0 + br     )*(NW*5) + bc);
            float4 bh1 = *(const float4*)(Bh + (size_t)(k0 + br + 16)*(NW*5) + bc);
            float4 bl0 = *(const float4*)(Bl + (size_t)(k0 + br     )*(NW*5) + bc);
            float4 bl1 = *(const float4*)(Bl + (size_t)(k0 + br + 16)*(NW*5) + bc);
            __syncthreads();
            *(float4*)&As_hi[(ar     )*LDA_S + ac] = h0;
            *(float4*)&As_hi[(ar + 32)*LDA_S + ac] = h1;
            *(float4*)&As_hi[(ar + 64)*LDA_S + ac] = h2;
            *(float4*)&As_hi[(ar + 96)*LDA_S + ac] = h3;
            *(float4*)&As_lo[(ar     )*LDA_S + ac] = l0;
            *(float4*)&As_lo[(ar + 32)*LDA_S + ac] = l1;
            *(float4*)&As_lo[(ar + 64)*LDA_S + ac] = l2;
            *(float4*)&As_lo[(ar + 96)*LDA_S + ac] = l3;
            *(float4*)&Bs_hi[(br     )*LDB_S + bc] = bh0;
            *(float4*)&Bs_hi[(br + 16)*LDB_S + bc] = bh1;
            *(float4*)&Bs_lo[(br     )*LDB_S + bc] = bl0;
            *(float4*)&Bs_lo[(br + 16)*LDB_S + bc] = bl1;
            __syncthreads();

#pragma unroll
            for (int kk = 0; kk < TBK; kk += 8) {
                u32 ahi[2][4], alo[2][4];
#pragma unroll
                for (int mt = 0; mt < 2; ++mt) {
                    int r0 = warpM*32 + mt*16;
                    ahi[mt][0] = __float_as_uint(As_hi[(r0 + grp    )*LDA_S + kk + tig    ]);
                    ahi[mt][1] = __float_as_uint(As_hi[(r0 + grp + 8)*LDA_S + kk + tig    ]);
                    ahi[mt][2] = __float_as_uint(As_hi[(r0 + grp    )*LDA_S + kk + tig + 4]);
                    ahi[mt][3] = __float_as_uint(As_hi[(r0 + grp + 8)*LDA_S + kk + tig + 4]);
                    alo[mt][0] = __float_as_uint(As_lo[(r0 + grp    )*LDA_S + kk + tig    ]);
                    alo[mt][1] = __float_as_uint(As_lo[(r0 + grp + 8)*LDA_S + kk + tig    ]);
                    alo[mt][2] = __float_as_uint(As_lo[(r0 + grp    )*LDA_S + kk + tig + 4]);
                    alo[mt][3] = __float_as_uint(As_lo[(r0 + grp + 8)*LDA_S + kk + tig + 4]);
                }
                u32 bhi[4][2], blo[4][2];
#pragma unroll
                for (int nt = 0; nt < 4; ++nt) {
                    int c0 = warpN*32 + nt*8 + grp;
                    bhi[nt][0] = __float_as_uint(Bs_hi[(kk + tig    )*LDB_S + c0]);
                    bhi[nt][1] = __float_as_uint(Bs_hi[(kk + tig + 4)*LDB_S + c0]);
                    blo[nt][0] = __float_as_uint(Bs_lo[(kk + tig    )*LDB_S + c0]);
                    blo[nt][1] = __float_as_uint(Bs_lo[(kk + tig + 4)*LDB_S + c0]);
                }
#pragma unroll
                for (int mt = 0; mt < 2; ++mt)
#pragma unroll
                    for (int nt = 0; nt < 4; ++nt) {
                        mma_tf32(acc[mt][nt], ahi[mt][0],ahi[mt][1],ahi[mt][2],ahi[mt][3],
                                 bhi[nt][0],bhi[nt][1]);
                        mma_tf32(acc[mt][nt], ahi[mt][0],ahi[mt][1],ahi[mt][2],ahi[mt][3],
                                 blo[nt][0],blo[nt][1]);
                        mma_tf32(acc[mt][nt], alo[mt][0],alo[mt][1],alo[mt][2],alo[mt][3],
                                 bhi[nt][0],bhi[nt][1]);
                    }
            }
        }

#pragma unroll
        for (int mt = 0; mt < 2; ++mt) {
#pragma unroll
            for (int nt = 0; nt < 4; ++nt) {
                int row0 = by*TBM + warpM*32 + mt*16 + grp;
                int col0 = bx*TBN + warpN*32 + nt*8 + 2*tig;
                float vals[4] = {acc[mt][nt].x, acc[mt][nt].y, acc[mt][nt].z, acc[mt][nt].w};
#pragma unroll
                for (int e = 0; e < 4; ++e) {
                    int row = row0 + (e >> 1)*8;
                    int col = col0 + (e & 1);
                    int m = row/5, ii = row%5, ww = col/5, jj = col%5;
                    g_sim[((size_t)(m*NW + ww))*25 + ii*5 + jj] = vals[e];
                }
            }
        }
    } else {
        // ---------- comb GEMM: per-p (2048x64) = qfA_p(2048x640) * pfB_p(640x64), FFMA2 ----------
        int tile = by & 15;       // 0..15 -> 128 rows each
        int p    = by >> 4;       // 0..4
        float* As = sm;           // [16][128]
        float* Bs = sm + 16*128;  // [16][64]

        const float* A = g_qfA + p*CCH;            const int lda = 5*CCH;
        const float* B = g_pfB + (size_t)p*CCH*NW; const int ldb = NW;

        int arow = tid >> 2;
        int acol = (tid & 3) * 4;
        int brow = tid >> 4;
        int bcol = (tid & 15) * 4;
        int ty = tid >> 4, tx = tid & 15;

        u64 acc[4][4];
#pragma unroll
        for (int i = 0; i < 4; ++i)
#pragma unroll
            for (int j = 0; j < 4; ++j) acc[i][j] = 0ull;

        const float* Ab = A + (size_t)(tile*128)*lda;

        for (int k0 = 0; k0 < CCH; k0 += 16) {
            float4 a0 = *(const float4*)(Ab + (size_t)arow*lda + k0 + acol);
            float4 a1 = *(const float4*)(Ab + (size_t)(arow+64)*lda + k0 + acol);
            float4 b0 = *(const float4*)(B  + (size_t)(k0+brow)*ldb + bcol);
            __syncthreads();
            As[(acol+0)*128 + arow]    = a0.x; As[(acol+1)*128 + arow]    = a0.y;
            As[(acol+2)*128 + arow]    = a0.z; As[(acol+3)*128 + arow]    = a0.w;
            As[(acol+0)*128 + arow+64] = a1.x; As[(acol+1)*128 + arow+64] = a1.y;
            As[(acol+2)*128 + arow+64] = a1.z; As[(acol+3)*128 + arow+64] = a1.w;
            *(float4*)&Bs[brow*64 + bcol] = b0;
            __syncthreads();
#pragma unroll
            for (int k = 0; k < 16; ++k) {
                const u64* ap = (const u64*)&As[k*128 + ty*8];
                u64 a2[4] = {ap[0], ap[1], ap[2], ap[3]};
                float4 bv = *(const float4*)&Bs[k*64 + tx*4];
                u64 b2[4] = {pack2(bv.x,bv.x), pack2(bv.y,bv.y),
                             pack2(bv.z,bv.z), pack2(bv.w,bv.w)};
#pragma unroll
                for (int ip = 0; ip < 4; ++ip)
#pragma unroll
                    for (int j = 0; j < 4; ++j) ffma2(acc[ip][j], a2[ip], b2[j]);
            }
        }

        int row0 = tile*128 + ty*8;
        int col0 = tx*4;
#pragma unroll
        for (int ip = 0; ip < 4; ++ip)
#pragma unroll
            for (int j = 0; j < 4; ++j) {
                float lo, hi; unpack2(acc[ip][j], lo, hi);
                int r_lo = row0 + 2*ip, r_hi = r_lo + 1;
                int cc = col0 + j;
                g_comb[(size_t)r_lo*(NW*5) + cc*5 + p] = lo;
                g_comb[(size_t)r_hi*(NW*5) + cc*5 + p] = hi;
            }
    }
}

// ---------------- Kernel 3: multiplicative Sinkhorn (scalar, rescaled kernel) ----------------
// K' = exp(20*sim)  (= K_ref * e^20; u absorbs the constant, flow identical each iter).
// Range analysis: all sums/iterates stay in fp32 normal range -> no clamps needed.
__global__ void __launch_bounds__(256) sinkhorn_kernel(float* __restrict__ out) {
    int t = blockIdx.x*256 + threadIdx.x;   // m*64 + w

    float a[5]; float ws = 0.f;
#pragma unroll
    for (int p = 0; p < 5; ++p) {
        float wv = fmaxf(g_comb[(size_t)t*5 + p], 0.f) + 0.00101f;
        a[p] = wv; ws += wv;
    }
    float sc = __fdividef(5.f, ws);
#pragma unroll
    for (int p = 0; p < 5; ++p) a[p] *= sc;

    float K[25];
    const float* sp = g_sim + (size_t)t*25;
#pragma unroll
    for (int e = 0; e < 25; ++e) K[e] = __expf(20.f * sp[e]);

    float u[5], v[5];
#pragma unroll
    for (int j = 0; j < 5; ++j) v[j] = 1.f;

#pragma unroll 1
    for (int it = 0; it < NITER; ++it) {
#pragma unroll
        for (int i = 0; i < 5; ++i) {
            float s = K[i*5+0]*v[0];
            s = fmaf(K[i*5+1], v[1], s);
            s = fmaf(K[i*5+2], v[2], s);
            s = fmaf(K[i*5+3], v[3], s);
            s = fmaf(K[i*5+4], v[4], s);
            u[i] = __fdividef(a[i], s);
        }
#pragma unroll
        for (int j = 0; j < 5; ++j) {
            float s = K[0*5+j]*u[0];
            s = fmaf(K[1*5+j], u[1], s);
            s = fmaf(K[2*5+j], u[2], s);
            s = fmaf(K[3*5+j], u[3], s);
            s = fmaf(K[4*5+j], u[4], s);
            v[j] = __fdividef(a[j], s);
        }
    }

    float L = 0.f;
#pragma unroll
    for (int i = 0; i < 5; ++i) {
        float ui = u[i];
#pragma unroll
        for (int j = 0; j < 5; ++j)
            L = fmaf(sp[i*5+j] * ui, K[i*5+j]*v[j], L);
    }
    out[t] = L * 2.5f;
}

// ---------------- launch ----------------
extern "C" void kernel_launch(void* const* d_in, const int* in_sizes, int n_in,
                              void* d_out, int out_size) {
    const float* proto = (const float*)d_in[0];
    const float* query = (const float*)d_in[1];
    if (n_in >= 2 && in_sizes[0] > in_sizes[1]) {
        proto = (const float*)d_in[1];
        query = (const float*)d_in[0];
    }
    float* out = (float*)d_out;

    static bool attr_set = false;
    if (!attr_set) {
        cudaFuncSetAttribute(feat_kernel, cudaFuncAttributeMaxDynamicSharedMemorySize, 64000);
        cudaFuncSetAttribute(gemm_mega, cudaFuncAttributeMaxDynamicSharedMemorySize, SMEM_GEMM);
        attr_set = true;
    }

    feat_kernel<<<NQ + NW, 640, 64000>>>(proto, query);
    gemm_mega<<<dim3(6, 80), 256, SMEM_GEMM>>>();   // bx<5: sim tiles; bx==5: comb (by = tile + 16*p)
    sinkhorn_kernel<<<(NQ*NW)/256, 256>>>(out);
}

// round 6
// speedup vs baseline: 1.2749x; 1.1209x over previous
#include <cuda_runtime.h>
#include <math.h>
#include <stdint.h>

#define NQ   2048
#define NW   64
#define CCH  640
#define NITER 100

typedef unsigned long long u64;
typedef unsigned int u32;

// ---------------- small helpers ----------------
__device__ __forceinline__ u64 pack2(float lo, float hi) {
    u64 r; asm("mov.b64 %0, {%1,%2};" : "=l"(r) : "f"(lo), "f"(hi)); return r;
}
__device__ __forceinline__ void unpack2(u64 v, float& lo, float& hi) {
    asm("mov.b64 {%0,%1}, %2;" : "=f"(lo), "=f"(hi) : "l"(v));
}
__device__ __forceinline__ void ffma2(u64& d, u64 a, u64 b) {
    asm("fma.rn.f32x2 %0, %1, %2, %0;" : "+l"(d) : "l"(a), "l"(b));
}
__device__ __forceinline__ u32 to_tf32_bits(float x) {
    u32 r; asm("cvt.rna.tf32.f32 %0, %1;" : "=r"(r) : "f"(x)); return r;
}
__device__ __forceinline__ void mma_tf32(float4& d, u32 a0,u32 a1,u32 a2,u32 a3, u32 b0,u32 b1) {
    asm("mma.sync.aligned.m16n8k8.row.col.f32.tf32.tf32.f32 "
        "{%0,%1,%2,%3},{%4,%5,%6,%7},{%8,%9},{%0,%1,%2,%3};"
        : "+f"(d.x),"+f"(d.y),"+f"(d.z),"+f"(d.w)
        : "r"(a0),"r"(a1),"r"(a2),"r"(a3),"r"(b0),"r"(b1));
}

// ---------------- scratch ----------------
__device__ float g_qnA_hi[(NQ*5)*CCH];  // tf32-rounded normalized query feats
__device__ float g_qnA_lo[(NQ*5)*CCH];  // residual
__device__ float g_pnB_hi[CCH*(NW*5)];  // [c][w*5+j]
__device__ float g_pnB_lo[CCH*(NW*5)];
__device__ float g_qfA[(NQ*5)*CCH];     // raw query features, row (m*5+p), col c
__device__ float g_pfB[5*CCH*NW];       // raw proto features [p][c][w]
__device__ float g_sim[(size_t)NQ*NW*25];  // [m][w][i][j]
__device__ float g_comb[(size_t)NQ*NW*5];  // [m][w][p]

// ---------------- Kernel 1: patch-pool features (per-warp staging) ----------------
__global__ void __launch_bounds__(640) feat_kernel(const float* __restrict__ proto,
                                                   const float* __restrict__ query) {
    extern __shared__ float simg[];   // 16000 floats; warp w owns [w*800, w*800+800)
    int b = blockIdx.x;               // 0..2047 query, 2048..2111 proto
    int c = threadIdx.x;              // channel 0..639
    int lane = c & 31, wid = c >> 5;  // 20 warps

    const float* base = (b < NQ) ? (query + (size_t)b*CCH*25)
                                 : (proto + (size_t)(b-NQ)*CCH*25);
    // warp w stages channels [w*32, w*32+32): 800 contiguous floats (16B-aligned)
    {
        const float4* src4 = (const float4*)(base + wid*800);
        float4* dst4 = (float4*)(simg + wid*800);
#pragma unroll
        for (int i = lane; i < 200; i += 32) dst4[i] = src4[i];
    }
    __syncwarp();

    float v[25];
    const float* mych = simg + wid*800 + lane*25;
#pragma unroll
    for (int k = 0; k < 25; ++k) v[k] = mych[k];   // 25*lane mod 32 bijective: conflict-free

    float s02[5], s24[5], s14[5];
#pragma unroll
    for (int col = 0; col < 5; ++col) {
        s02[col] = v[col]    + v[5+col]  + v[10+col];
        s24[col] = v[10+col] + v[15+col] + v[20+col];
        s14[col] = v[5+col] + v[10+col] + v[15+col] + v[20+col];
    }
    float fea[5];
    fea[0] = (s02[0]+s02[1]+s02[2]) * (1.f/9.f);
    fea[1] = (s24[0]+s24[1]+s24[2]) * (1.f/9.f);
    fea[2] = (s14[1]+s14[2]+s14[3]+s14[4]) * (1.f/16.f);
    fea[3] = (s02[2]+s02[3]+s02[4]) * (1.f/9.f);
    fea[4] = (s24[2]+s24[3]+s24[4]) * (1.f/9.f);

    if (b < NQ) {
#pragma unroll
        for (int p = 0; p < 5; ++p) g_qfA[(size_t)(b*5+p)*CCH + c] = fea[p];
    } else {
        int w = b - NQ;
#pragma unroll
        for (int p = 0; p < 5; ++p) g_pfB[((size_t)p*CCH + c)*NW + w] = fea[p];
    }

    __shared__ float sred[5][20];
    __shared__ float sstat[5];

    float r[5];
#pragma unroll
    for (int p = 0; p < 5; ++p) r[p] = fea[p];
#pragma unroll
    for (int o = 16; o; o >>= 1)
#pragma unroll
        for (int p = 0; p < 5; ++p) r[p] += __shfl_down_sync(0xffffffffu, r[p], o);
    if (lane == 0)
#pragma unroll
        for (int p = 0; p < 5; ++p) sred[p][wid] = r[p];
    __syncthreads();
    if (c < 5) {
        float s = 0.f;
        for (int q = 0; q < 20; ++q) s += sred[c][q];
        sstat[c] = s * (1.f/640.f);
    }
    __syncthreads();
    float cent[5];
#pragma unroll
    for (int p = 0; p < 5; ++p) cent[p] = fea[p] - sstat[p];

#pragma unroll
    for (int p = 0; p < 5; ++p) r[p] = cent[p]*cent[p];
#pragma unroll
    for (int o = 16; o; o >>= 1)
#pragma unroll
        for (int p = 0; p < 5; ++p) r[p] += __shfl_down_sync(0xffffffffu, r[p], o);
    __syncthreads();
    if (lane == 0)
#pragma unroll
        for (int p = 0; p < 5; ++p) sred[p][wid] = r[p];
    __syncthreads();
    if (c < 5) {
        float s = 0.f;
        for (int q = 0; q < 20; ++q) s += sred[c][q];
        sstat[c] = 1.f / fmaxf(sqrtf(s), 1e-8f);
    }
    __syncthreads();

    if (b < NQ) {
#pragma unroll
        for (int i = 0; i < 5; ++i) {
            float q = cent[i]*sstat[i];
            u32 h = to_tf32_bits(q);
            size_t idx = (size_t)(b*5+i)*CCH + c;
            g_qnA_hi[idx] = __uint_as_float(h);
            g_qnA_lo[idx] = q - __uint_as_float(h);
        }
    } else {
        int w = b - NQ;
#pragma unroll
        for (int j = 0; j < 5; ++j) {
            float q = cent[j]*sstat[j];
            u32 h = to_tf32_bits(q);
            size_t idx = (size_t)c*(NW*5) + w*5 + j;
            g_pnB_hi[idx] = __uint_as_float(h);
            g_pnB_lo[idx] = q - __uint_as_float(h);
        }
    }
}

// ---------------- Kernel 2: mega GEMM  (bx<5: sim tf32x3, bx==5: comb FFMA2) ----------------
#define TBM 128
#define TBN 64
#define TBK 32
#define LDA_S 36
#define LDB_S 68
#define SMEM_GEMM ((2*TBM*LDA_S + 2*TBK*LDB_S)*4)   // 54272 B

__global__ void __launch_bounds__(256) gemm_mega() {
    extern __shared__ float sm[];
    int tid = threadIdx.x;
    int bx = blockIdx.x, by = blockIdx.y;

    if (bx < 5) {
        float* As_hi = sm;
        float* As_lo = sm + TBM*LDA_S;
        float* Bs_hi = sm + 2*TBM*LDA_S;
        float* Bs_lo = sm + 2*TBM*LDA_S + TBK*LDB_S;

        int lane = tid & 31;
        int w = tid >> 5;
        int warpM = w & 3;
        int warpN = w >> 2;
        int grp = lane >> 2;
        int tig = lane & 3;

        float4 acc[2][4];
#pragma unroll
        for (int mt = 0; mt < 2; ++mt)
#pragma unroll
            for (int nt = 0; nt < 4; ++nt) acc[mt][nt] = make_float4(0.f,0.f,0.f,0.f);

        const float* Ah = g_qnA_hi + (size_t)(by*TBM)*CCH;
        const float* Al = g_qnA_lo + (size_t)(by*TBM)*CCH;
        const float* Bh = g_pnB_hi + bx*TBN;
        const float* Bl = g_pnB_lo + bx*TBN;

        int ar = tid >> 3;            // 0..31
        int ac = (tid & 7) * 4;       // 0..28
        int br = tid >> 4;            // 0..15
        int bc = (tid & 15) * 4;      // 0..60

        for (int k0 = 0; k0 < CCH; k0 += TBK) {
            float4 h0 = *(const float4*)(Ah + (size_t)(ar     )*CCH + k0 + ac);
            float4 h1 = *(const float4*)(Ah + (size_t)(ar + 32)*CCH + k0 + ac);
            float4 h2 = *(const float4*)(Ah + (size_t)(ar + 64)*CCH + k0 + ac);
            float4 h3 = *(const float4*)(Ah + (size_t)(ar + 96)*CCH + k0 + ac);
            float4 l0 = *(const float4*)(Al + (size_t)(ar     )*CCH + k0 + ac);
            float4 l1 = *(const float4*)(Al + (size_t)(ar + 32)*CCH + k0 + ac);
            float4 l2 = *(const float4*)(Al + (size_t)(ar + 64)*CCH + k0 + ac);
            float4 l3 = *(const float4*)(Al + (size_t)(ar + 96)*CCH + k0 + ac);
            float4 bh0 = *(const float4*)(Bh + (size_t)(k0 + br     )*(NW*5) + bc);
            float4 bh1 = *(const float4*)(Bh + (size_t)(k0 + br + 16)*(NW*5) + bc);
            float4 bl0 = *(const float4*)(Bl + (size_t)(k0 + br     )*(NW*5) + bc);
            float4 bl1 = *(const float4*)(Bl + (size_t)(k0 + br + 16)*(NW*5) + bc);
            __syncthreads();
            *(float4*)&As_hi[(ar     )*LDA_S + ac] = h0;
            *(float4*)&As_hi[(ar + 32)*LDA_S + ac] = h1;
            *(float4*)&As_hi[(ar + 64)*LDA_S + ac] = h2;
            *(float4*)&As_hi[(ar + 96)*LDA_S + ac] = h3;
            *(float4*)&As_lo[(ar     )*LDA_S + ac] = l0;
            *(float4*)&As_lo[(ar + 32)*LDA_S + ac] = l1;
            *(float4*)&As_lo[(ar + 64)*LDA_S + ac] = l2;
            *(float4*)&As_lo[(ar + 96)*LDA_S + ac] = l3;
            *(float4*)&Bs_hi[(br     )*LDB_S + bc] = bh0;
            *(float4*)&Bs_hi[(br + 16)*LDB_S + bc] = bh1;
            *(float4*)&Bs_lo[(br     )*LDB_S + bc] = bl0;
            *(float4*)&Bs_lo[(br + 16)*LDB_S + bc] = bl1;
            __syncthreads();

#pragma unroll
            for (int kk = 0; kk < TBK; kk += 8) {
                u32 ahi[2][4], alo[2][4];
#pragma unroll
                for (int mt = 0; mt < 2; ++mt) {
                    int r0 = warpM*32 + mt*16;
                    ahi[mt][0] = __float_as_uint(As_hi[(r0 + grp    )*LDA_S + kk + tig    ]);
                    ahi[mt][1] = __float_as_uint(As_hi[(r0 + grp + 8)*LDA_S + kk + tig    ]);
                    ahi[mt][2] = __float_as_uint(As_hi[(r0 + grp    )*LDA_S + kk + tig + 4]);
                    ahi[mt][3] = __float_as_uint(As_hi[(r0 + grp + 8)*LDA_S + kk + tig + 4]);
                    alo[mt][0] = __float_as_uint(As_lo[(r0 + grp    )*LDA_S + kk + tig    ]);
                    alo[mt][1] = __float_as_uint(As_lo[(r0 + grp + 8)*LDA_S + kk + tig    ]);
                    alo[mt][2] = __float_as_uint(As_lo[(r0 + grp    )*LDA_S + kk + tig + 4]);
                    alo[mt][3] = __float_as_uint(As_lo[(r0 + grp + 8)*LDA_S + kk + tig + 4]);
                }
                u32 bhi[4][2], blo[4][2];
#pragma unroll
                for (int nt = 0; nt < 4; ++nt) {
                    int c0 = warpN*32 + nt*8 + grp;
                    bhi[nt][0] = __float_as_uint(Bs_hi[(kk + tig    )*LDB_S + c0]);
                    bhi[nt][1] = __float_as_uint(Bs_hi[(kk + tig + 4)*LDB_S + c0]);
                    blo[nt][0] = __float_as_uint(Bs_lo[(kk + tig    )*LDB_S + c0]);
                    blo[nt][1] = __float_as_uint(Bs_lo[(kk + tig + 4)*LDB_S + c0]);
                }
#pragma unroll
                for (int mt = 0; mt < 2; ++mt)
#pragma unroll
                    for (int nt = 0; nt < 4; ++nt) {
                        mma_tf32(acc[mt][nt], ahi[mt][0],ahi[mt][1],ahi[mt][2],ahi[mt][3],
                                 bhi[nt][0],bhi[nt][1]);
                        mma_tf32(acc[mt][nt], ahi[mt][0],ahi[mt][1],ahi[mt][2],ahi[mt][3],
                                 blo[nt][0],blo[nt][1]);
                        mma_tf32(acc[mt][nt], alo[mt][0],alo[mt][1],alo[mt][2],alo[mt][3],
                                 bhi[nt][0],bhi[nt][1]);
                    }
            }
        }

#pragma unroll
        for (int mt = 0; mt < 2; ++mt) {
#pragma unroll
            for (int nt = 0; nt < 4; ++nt) {
                int row0 = by*TBM + warpM*32 + mt*16 + grp;
                int col0 = bx*TBN + warpN*32 + nt*8 + 2*tig;
                float vals[4] = {acc[mt][nt].x, acc[mt][nt].y, acc[mt][nt].z, acc[mt][nt].w};
#pragma unroll
                for (int e = 0; e < 4; ++e) {
                    int row = row0 + (e >> 1)*8;
                    int col = col0 + (e & 1);
                    int m = row/5, ii = row%5, ww = col/5, jj = col%5;
                    g_sim[((size_t)(m*NW + ww))*25 + ii*5 + jj] = vals[e];
                }
            }
        }
    } else {
        // ---------- comb GEMM: per-p (2048x64) = qfA_p(2048x640) * pfB_p(640x64), FFMA2 ----------
        int tile = by & 15;
        int p    = by >> 4;
        float* As = sm;           // [16][128]
        float* Bs = sm + 16*128;  // [16][64]

        const float* A = g_qfA + p*CCH;            const int lda = 5*CCH;
        const float* B = g_pfB + (size_t)p*CCH*NW; const int ldb = NW;

        int arow = tid >> 2;
        int acol = (tid & 3) * 4;
        int brow = tid >> 4;
        int bcol = (tid & 15) * 4;
        int ty = tid >> 4, tx = tid & 15;

        u64 acc[4][4];
#pragma unroll
        for (int i = 0; i < 4; ++i)
#pragma unroll
            for (int j = 0; j < 4; ++j) acc[i][j] = 0ull;

        const float* Ab = A + (size_t)(tile*128)*lda;

        for (int k0 = 0; k0 < CCH; k0 += 16) {
            float4 a0 = *(const float4*)(Ab + (size_t)arow*lda + k0 + acol);
            float4 a1 = *(const float4*)(Ab + (size_t)(arow+64)*lda + k0 + acol);
            float4 b0 = *(const float4*)(B  + (size_t)(k0+brow)*ldb + bcol);
            __syncthreads();
            As[(acol+0)*128 + arow]    = a0.x; As[(acol+1)*128 + arow]    = a0.y;
            As[(acol+2)*128 + arow]    = a0.z; As[(acol+3)*128 + arow]    = a0.w;
            As[(acol+0)*128 + arow+64] = a1.x; As[(acol+1)*128 + arow+64] = a1.y;
            As[(acol+2)*128 + arow+64] = a1.z; As[(acol+3)*128 + arow+64] = a1.w;
            *(float4*)&Bs[brow*64 + bcol] = b0;
            __syncthreads();
#pragma unroll
            for (int k = 0; k < 16; ++k) {
                const u64* ap = (const u64*)&As[k*128 + ty*8];
                u64 a2[4] = {ap[0], ap[1], ap[2], ap[3]};
                float4 bv = *(const float4*)&Bs[k*64 + tx*4];
                u64 b2[4] = {pack2(bv.x,bv.x), pack2(bv.y,bv.y),
                             pack2(bv.z,bv.z), pack2(bv.w,bv.w)};
#pragma unroll
                for (int ip = 0; ip < 4; ++ip)
#pragma unroll
                    for (int j = 0; j < 4; ++j) ffma2(acc[ip][j], a2[ip], b2[j]);
            }
        }

        int row0 = tile*128 + ty*8;
        int col0 = tx*4;
#pragma unroll
        for (int ip = 0; ip < 4; ++ip)
#pragma unroll
            for (int j = 0; j < 4; ++j) {
                float lo, hi; unpack2(acc[ip][j], lo, hi);
                int r_lo = row0 + 2*ip, r_hi = r_lo + 1;
                int cc = col0 + j;
                g_comb[(size_t)r_lo*(NW*5) + cc*5 + p] = lo;
                g_comb[(size_t)r_hi*(NW*5) + cc*5 + p] = hi;
            }
    }
}

// ---------------- Kernel 3: Sinkhorn (scalar, rescaled) + convergence early-exit ----------------
// K' = exp(20*sim); u absorbs the e^20; flow identical. Once the v-iterate stops moving
// (contraction fixed point), remaining reference iterations are numerically the identity,
// so breaking reproduces the 100-iter result within fp32 noise (<< 1e-3 tolerance).
__global__ void __launch_bounds__(256) sinkhorn_kernel(float* __restrict__ out) {
    int t = blockIdx.x*256 + threadIdx.x;   // m*64 + w

    float a[5]; float ws = 0.f;
#pragma unroll
    for (int p = 0; p < 5; ++p) {
        float wv = fmaxf(g_comb[(size_t)t*5 + p], 0.f) + 0.00101f;
        a[p] = wv; ws += wv;
    }
    float sc = __fdividef(5.f, ws);
#pragma unroll
    for (int p = 0; p < 5; ++p) a[p] *= sc;

    float K[25];
    const float* sp = g_sim + (size_t)t*25;
#pragma unroll
    for (int e = 0; e < 25; ++e) K[e] = __expf(20.f * sp[e]);

    float u[5], v[5];
#pragma unroll
    for (int j = 0; j < 5; ++j) v[j] = 1.f;

#pragma unroll 1
    for (int chunk = 0; chunk < 10; ++chunk) {
        float vs[5];
#pragma unroll
        for (int j = 0; j < 5; ++j) vs[j] = v[j];

#pragma unroll
        for (int s = 0; s < 10; ++s) {
#pragma unroll
            for (int i = 0; i < 5; ++i) {
                float acc = K[i*5+0]*v[0];
                acc = fmaf(K[i*5+1], v[1], acc);
                acc = fmaf(K[i*5+2], v[2], acc);
                acc = fmaf(K[i*5+3], v[3], acc);
                acc = fmaf(K[i*5+4], v[4], acc);
                u[i] = __fdividef(a[i], acc);
            }
#pragma unroll
            for (int j = 0; j < 5; ++j) {
                float acc = K[0*5+j]*u[0];
                acc = fmaf(K[1*5+j], u[1], acc);
                acc = fmaf(K[2*5+j], u[2], acc);
                acc = fmaf(K[3*5+j], u[3], acc);
                acc = fmaf(K[4*5+j], u[4], acc);
                v[j] = __fdividef(a[j], acc);
            }
        }

        // converged if every v moved < 1e-6 relative over the whole 10-iter chunk
        bool conv = true;
#pragma unroll
        for (int j = 0; j < 5; ++j)
            conv = conv && (fabsf(v[j] - vs[j]) <= 1e-6f * v[j]);
        if (__all_sync(0xffffffffu, conv)) break;
    }

    float L = 0.f;
#pragma unroll
    for (int i = 0; i < 5; ++i) {
        float ui = u[i];
#pragma unroll
        for (int j = 0; j < 5; ++j)
            L = fmaf(sp[i*5+j] * ui, K[i*5+j]*v[j], L);
    }
    out[t] = L * 2.5f;
}

// ---------------- launch ----------------
extern "C" void kernel_launch(void* const* d_in, const int* in_sizes, int n_in,
                              void* d_out, int out_size) {
    const float* proto = (const float*)d_in[0];
    const float* query = (const float*)d_in[1];
    if (n_in >= 2 && in_sizes[0] > in_sizes[1]) {
        proto = (const float*)d_in[1];
        query = (const float*)d_in[0];
    }
    float* out = (float*)d_out;

    static bool attr_set = false;
    if (!attr_set) {
        cudaFuncSetAttribute(feat_kernel, cudaFuncAttributeMaxDynamicSharedMemorySize, 64000);
        cudaFuncSetAttribute(gemm_mega, cudaFuncAttributeMaxDynamicSharedMemorySize, SMEM_GEMM);
        attr_set = true;
    }

    feat_kernel<<<NQ + NW, 640, 64000>>>(proto, query);
    gemm_mega<<<dim3(6, 80), 256, SMEM_GEMM>>>();   // bx<5: sim tiles; bx==5: comb
    sinkhorn_kernel<<<(NQ*NW)/256, 256>>>(out);
}